// round 5
// baseline (speedup 1.0000x reference)
#include <cuda_runtime.h>
#include <math.h>

// Problem constants (fixed shapes)
#define B_  4
#define C_  32      // C_IN == C_OUT == 32
#define T_  48
#define N_  2000
#define E_  16000
#define BT_ (B_ * T_)    // 192

#define TSTRIDE 36       // padded smem tile row stride (words)

// ---------------------------------------------------------------------------
// Scratch (device globals — no runtime allocation allowed)
// ---------------------------------------------------------------------------
__device__ float g_xw[BT_ * N_ * C_];    // xw = relu(conv1(x)) @ gcn_w, layout [g][n][c]
__device__ float g_gout[BT_ * N_ * C_];  // GCN output, layout [g][n][c]
__device__ int   g_off[N_ + 1];
__device__ int   g_csr_src[E_];
__device__ float g_csr_w[E_];
__device__ float g_invdeg[N_];

// ---------------------------------------------------------------------------
// f32x2 packed-math helpers (Blackwell FFMA2: 2 fp32 FMA per issue slot)
// ---------------------------------------------------------------------------
__device__ __forceinline__ unsigned long long dup2(float x) {
    unsigned long long r;
    unsigned u = __float_as_uint(x);
    asm("mov.b64 %0, {%1, %1};" : "=l"(r) : "r"(u));
    return r;
}
__device__ __forceinline__ void ffma2(unsigned long long& acc,
                                      unsigned long long a,
                                      unsigned long long b) {
    asm("fma.rn.f32x2 %0, %1, %2, %0;" : "+l"(acc) : "l"(a), "l"(b));
}
__device__ __forceinline__ float2 unpack2(unsigned long long v) {
    unsigned lo, hi;
    asm("mov.b64 {%0, %1}, %2;" : "=r"(lo), "=r"(hi) : "l"(v));
    return make_float2(__uint_as_float(lo), __uint_as_float(hi));
}

// ---------------------------------------------------------------------------
// Single-kernel edge preprocessing (unchanged from R2): dtype-detect,
// smem histogram, block scan -> CSR offsets + degree terms, CSR fill.
// ---------------------------------------------------------------------------
__global__ void __launch_bounds__(1024) k_prep(const void* __restrict__ edges) {
    __shared__ int   s_cnt[2048];
    __shared__ int   s_off[2048];
    __shared__ float s_dinv[2048];
    __shared__ int   s_wsum[32];
    __shared__ int   s_is64;

    int tid = threadIdx.x;
    if (tid == 0) {
        const int* q = (const int*)edges;
        int ok = 1;
        #pragma unroll 1
        for (int i = 0; i < 64; i++) {
            if (q[2 * i + 1] != 0) { ok = 0; break; }
        }
        s_is64 = ok;
    }
    s_cnt[tid] = 0;
    s_cnt[tid + 1024] = 0;
    __syncthreads();

    const int is64 = s_is64;
    int es[16], ed[16];
    #pragma unroll
    for (int i = 0; i < 16; i++) {
        int e = tid + i * 1024;
        if (e < E_) {
            int s, d;
            if (is64) {
                const long long* p = (const long long*)edges;
                s = (int)p[e];
                d = (int)p[E_ + e];
            } else {
                const int* p = (const int*)edges;
                s = p[e];
                d = p[E_ + e];
            }
            es[i] = s; ed[i] = d;
            atomicAdd(&s_cnt[d], 1);
        } else {
            es[i] = -1; ed[i] = -1;
        }
    }
    __syncthreads();

    int lane = tid & 31, wid = tid >> 5;
    int i0 = 2 * tid, i1 = 2 * tid + 1;
    int c0 = (i0 < N_) ? s_cnt[i0] : 0;
    int c1 = (i1 < N_) ? s_cnt[i1] : 0;
    int sum = c0 + c1;
    int incl = sum;
    #pragma unroll
    for (int o = 1; o < 32; o <<= 1) {
        int v = __shfl_up_sync(0xffffffffu, incl, o);
        if (lane >= o) incl += v;
    }
    if (lane == 31) s_wsum[wid] = incl;
    __syncthreads();
    if (wid == 0) {
        int w = s_wsum[lane];
        int wi = w;
        #pragma unroll
        for (int o = 1; o < 32; o <<= 1) {
            int v = __shfl_up_sync(0xffffffffu, wi, o);
            if (lane >= o) wi += v;
        }
        s_wsum[lane] = wi - w;
    }
    __syncthreads();
    int excl = s_wsum[wid] + incl - sum;
    if (i0 < N_) {
        s_off[i0] = excl;
        g_off[i0] = excl;
        float deg = (float)c0 + 1.0f;
        s_dinv[i0] = rsqrtf(deg);
        g_invdeg[i0] = 1.0f / deg;
    }
    if (i1 < N_) {
        int e1 = excl + c0;
        s_off[i1] = e1;
        g_off[i1] = e1;
        float deg = (float)c1 + 1.0f;
        s_dinv[i1] = rsqrtf(deg);
        g_invdeg[i1] = 1.0f / deg;
    }
    if (tid == 0) g_off[N_] = E_;
    __syncthreads();

    s_cnt[tid] = 0;
    s_cnt[tid + 1024] = 0;
    __syncthreads();

    #pragma unroll
    for (int i = 0; i < 16; i++) {
        if (ed[i] >= 0) {
            int d = ed[i], s = es[i];
            int pos = atomicAdd(&s_cnt[d], 1);
            int idx = s_off[d] + pos;
            g_csr_src[idx] = s;
            g_csr_w[idx] = s_dinv[s] * s_dinv[d];
        }
    }
}

// ---------------------------------------------------------------------------
// K1: fused  xw = relu(conv1(x) + b1) @ gcn_w   (FFMA2)
// Global loads coalesced; output staged through padded smem tile so the
// [n][c] store is fully coalesced.
// ---------------------------------------------------------------------------
__global__ void __launch_bounds__(128) k_conv1_gemm(
    const float* __restrict__ x,
    const float* __restrict__ w1,
    const float* __restrict__ b1,
    const float* __restrict__ gcn_w)
{
    __shared__ __align__(16) float w1s[C_ * 3 * C_];   // [(ci*3+k)*32 + co]
    __shared__ __align__(16) float gws[C_ * C_];       // [co*32 + c2]
    __shared__ __align__(16) float b1s[C_];
    __shared__ __align__(16) float tile[128 * TSTRIDE];

    int tid = threadIdx.x;
    for (int i = tid; i < C_ * 3 * C_; i += 128) {
        int co = i & 31;
        int rest = i >> 5;
        int k = rest % 3;
        int ci = rest / 3;
        w1s[i] = w1[(co * C_ + ci) * 3 + k];
    }
    for (int i = tid; i < C_ * C_; i += 128) gws[i] = gcn_w[i];
    if (tid < C_) b1s[tid] = b1[tid];
    __syncthreads();

    int n0 = blockIdx.x * 128;
    int n = n0 + tid;
    int t = blockIdx.y;
    int b = blockIdx.z;
    bool active = (n < N_);

    if (active) {
        unsigned long long h2[16];
        const unsigned long long* bp = (const unsigned long long*)b1s;
        #pragma unroll
        for (int q = 0; q < 16; q++) h2[q] = bp[q];

        const float* xp0 = x + ((b * C_) * T_ + t) * N_ + n;
        #pragma unroll 2
        for (int ci = 0; ci < C_; ci++) {
            const float* xp = xp0 + ci * (T_ * N_);
            #pragma unroll
            for (int k = 0; k < 3; k++) {
                int tt = t + k - 1;
                if (tt < 0 || tt >= T_) continue;
                unsigned long long xv2 = dup2(xp[(k - 1) * N_]);
                const ulonglong2* wp = (const ulonglong2*)&w1s[(ci * 3 + k) * C_];
                #pragma unroll
                for (int q = 0; q < 8; q++) {
                    ulonglong2 w = wp[q];
                    ffma2(h2[2 * q + 0], w.x, xv2);
                    ffma2(h2[2 * q + 1], w.y, xv2);
                }
            }
        }

        unsigned long long o2[16];
        #pragma unroll
        for (int q = 0; q < 16; q++) o2[q] = 0ull;

        #pragma unroll 1
        for (int q = 0; q < 16; q++) {
            float2 hp = unpack2(h2[q]);
            unsigned long long av = dup2(fmaxf(hp.x, 0.0f));
            unsigned long long bv = dup2(fmaxf(hp.y, 0.0f));
            const ulonglong2* ga = (const ulonglong2*)&gws[(2 * q + 0) * C_];
            const ulonglong2* gb = (const ulonglong2*)&gws[(2 * q + 1) * C_];
            #pragma unroll
            for (int j = 0; j < 8; j++) {
                ulonglong2 wa = ga[j];
                ffma2(o2[2 * j + 0], wa.x, av);
                ffma2(o2[2 * j + 1], wa.y, av);
            }
            #pragma unroll
            for (int j = 0; j < 8; j++) {
                ulonglong2 wb = gb[j];
                ffma2(o2[2 * j + 0], wb.x, bv);
                ffma2(o2[2 * j + 1], wb.y, bv);
            }
        }

        // stage to padded smem tile
        float2* tp = (float2*)&tile[tid * TSTRIDE];
        #pragma unroll
        for (int q = 0; q < 16; q++) {
            float2 v = unpack2(o2[q]);
            tp[q] = v;
        }
    }
    __syncthreads();

    // cooperative coalesced store
    int rows = min(128, N_ - n0);
    float* dst = g_xw + (((b * T_ + t) * N_) + n0) * C_;
    int total = rows * C_;
    for (int i = tid; i < total; i += 128) {
        dst[i] = tile[(i >> 5) * TSTRIDE + (i & 31)];
    }
}

// ---------------------------------------------------------------------------
// K2: GCN aggregation via CSR (unchanged). One warp per (graph, dst-node).
// ---------------------------------------------------------------------------
__global__ void __launch_bounds__(256) k_agg(const float* __restrict__ gcn_b) {
    int warp = threadIdx.x >> 5;
    int lane = threadIdx.x & 31;
    int n = blockIdx.x * 8 + warp;
    int g = blockIdx.y;
    if (n >= N_) return;

    int s0 = g_off[n];
    int s1 = g_off[n + 1];
    const float* __restrict__ xwg = g_xw + (size_t)g * N_ * C_;

    float accA = 0.0f, accB = 0.0f;
    int e = s0;
    for (; e + 1 < s1; e += 2) {
        int   sA = g_csr_src[e];
        int   sB = g_csr_src[e + 1];
        float wA = g_csr_w[e];
        float wB = g_csr_w[e + 1];
        float vA = __ldg(&xwg[sA * C_ + lane]);
        float vB = __ldg(&xwg[sB * C_ + lane]);
        accA += wA * vA;
        accB += wB * vB;
    }
    if (e < s1) {
        accA += g_csr_w[e] * __ldg(&xwg[g_csr_src[e] * C_ + lane]);
    }
    float acc = accA + accB + g_invdeg[n] * xwg[n * C_ + lane] + gcn_b[lane];
    g_gout[(size_t)g * N_ * C_ + n * C_ + lane] = acc;
}

// ---------------------------------------------------------------------------
// K3: conv2 over gout [g][n][c] -> out [B, C, T, N]   (FFMA2)
// Per-k smem tile staging: coalesced global loads, LDS.128 row reads.
// ---------------------------------------------------------------------------
__global__ void __launch_bounds__(128) k_conv2(
    const float* __restrict__ w2,
    const float* __restrict__ b2,
    float* __restrict__ out)
{
    __shared__ __align__(16) float w2s[C_ * 3 * C_];   // [(ci*3+k)*32 + co]
    __shared__ __align__(16) float b2s[C_];
    __shared__ __align__(16) float tile[128 * TSTRIDE];

    int tid = threadIdx.x;
    for (int i = tid; i < C_ * 3 * C_; i += 128) {
        int co = i & 31;
        int rest = i >> 5;
        int k = rest % 3;
        int ci = rest / 3;
        w2s[i] = w2[(co * C_ + ci) * 3 + k];
    }
    if (tid < C_) b2s[tid] = b2[tid];
    __syncthreads();

    int n0 = blockIdx.x * 128;
    int n = n0 + tid;
    int t = blockIdx.y;
    int b = blockIdx.z;
    bool active = (n < N_);
    int rows = min(128, N_ - n0);
    int total = rows * C_;

    unsigned long long o2[16];
    const unsigned long long* bp = (const unsigned long long*)b2s;
    #pragma unroll
    for (int q = 0; q < 16; q++) o2[q] = bp[q];

    #pragma unroll 1
    for (int k = 0; k < 3; k++) {
        int tt = t + k - 1;
        bool valid = (tt >= 0 && tt < T_);
        __syncthreads();   // protect tile from previous iteration
        if (valid) {
            const float* src = g_gout + (((b * T_ + tt) * N_) + n0) * C_;
            for (int i = tid; i < total; i += 128) {
                tile[(i >> 5) * TSTRIDE + (i & 31)] = src[i];
            }
        }
        __syncthreads();
        if (valid && active) {
            const float4* tp = (const float4*)&tile[tid * TSTRIDE];
            #pragma unroll
            for (int q4 = 0; q4 < 8; q4++) {
                float4 gv = tp[q4];
                float xv[4] = {gv.x, gv.y, gv.z, gv.w};
                #pragma unroll
                for (int j = 0; j < 4; j++) {
                    int ci = q4 * 4 + j;
                    unsigned long long v2 = dup2(xv[j]);
                    const ulonglong2* wp = (const ulonglong2*)&w2s[(ci * 3 + k) * C_];
                    #pragma unroll
                    for (int q = 0; q < 8; q++) {
                        ulonglong2 w = wp[q];
                        ffma2(o2[2 * q + 0], w.x, v2);
                        ffma2(o2[2 * q + 1], w.y, v2);
                    }
                }
            }
        }
    }

    if (active) {
        float* obase = out + ((b * C_) * T_ + t) * N_ + n;
        #pragma unroll
        for (int q = 0; q < 16; q++) {
            float2 v = unpack2(o2[q]);
            obase[(2 * q + 0) * (T_ * N_)] = v.x;
            obase[(2 * q + 1) * (T_ * N_)] = v.y;
        }
    }
}

// ---------------------------------------------------------------------------
// Launcher
// ---------------------------------------------------------------------------
extern "C" void kernel_launch(void* const* d_in, const int* in_sizes, int n_in,
                              void* d_out, int out_size) {
    const float* x     = (const float*)d_in[0];
    const void*  edges = d_in[1];
    const float* w1    = (const float*)d_in[2];
    const float* b1    = (const float*)d_in[3];
    const float* gcn_w = (const float*)d_in[4];
    const float* gcn_b = (const float*)d_in[5];
    const float* w2    = (const float*)d_in[6];
    const float* b2    = (const float*)d_in[7];
    float* out = (float*)d_out;

    k_prep<<<1, 1024>>>(edges);

    dim3 gconv((N_ + 127) / 128, T_, B_);
    k_conv1_gemm<<<gconv, 128>>>(x, w1, b1, gcn_w);

    dim3 gagg(N_ / 8, BT_);
    k_agg<<<gagg, 256>>>(gcn_b);

    k_conv2<<<gconv, 128>>>(w2, b2, out);
}

// round 6
// speedup vs baseline: 1.1250x; 1.1250x over previous
#include <cuda_runtime.h>
#include <math.h>

// Problem constants (fixed shapes)
#define B_  4
#define C_  32
#define T_  48
#define N_  2000
#define E_  16000
#define BT_ (B_ * T_)   // 192

#define PTSB 256        // points per conv block
#define NBLK 8          // ceil(2000/256)
#define HSTRIDE 264     // htile row stride (words)
#define XWSTRIDE 33     // xw transpose tile row stride (words)

// ---------------------------------------------------------------------------
// Scratch (device globals)
// ---------------------------------------------------------------------------
__device__ float g_xw[BT_ * N_ * C_];     // [g][n][c] (for gather)
__device__ float g_gout[BT_ * C_ * N_];   // [g][c][n] (for conv2 coalesced reads)
__device__ int   g_srcb[E_];
__device__ int   g_dstb[E_];
__device__ int   g_off[N_ + 1];
__device__ int   g_csr_src[E_];
__device__ float g_csr_w[E_];
__device__ float g_invdeg[N_];

// ---------------------------------------------------------------------------
// f32x2 helpers
// ---------------------------------------------------------------------------
__device__ __forceinline__ unsigned long long dup2(float x) {
    unsigned long long r;
    unsigned u = __float_as_uint(x);
    asm("mov.b64 %0, {%1, %1};" : "=l"(r) : "r"(u));
    return r;
}
__device__ __forceinline__ void ffma2(unsigned long long& acc,
                                      unsigned long long a,
                                      unsigned long long b) {
    asm("fma.rn.f32x2 %0, %1, %2, %0;" : "+l"(acc) : "l"(a), "l"(b));
}
__device__ __forceinline__ float2 unpack2(unsigned long long v) {
    unsigned lo, hi;
    asm("mov.b64 {%0, %1}, %2;" : "=r"(lo), "=r"(hi) : "l"(v));
    return make_float2(__uint_as_float(lo), __uint_as_float(hi));
}

// ---------------------------------------------------------------------------
// K1: fused conv1+relu+gcn_w GEMM, with CSR preprocessing fused in as one
// extra block (blockIdx.x == NBLK).
// Thread map: cog = tid&3 (co group of 8), ptg = tid>>2 (8 points).
// acc[pp][q]: f32x2 over point-pair (2pp,2pp+1), co = cog*8+q.
// ---------------------------------------------------------------------------
__global__ void __launch_bounds__(128) k_conv1(
    const float* __restrict__ x,
    const void*  __restrict__ edges,
    const float* __restrict__ w1,
    const float* __restrict__ b1,
    const float* __restrict__ gcn_w)
{
    __shared__ union {
        float pool[8448];                 // htile [32][264] / xwtile [256][33]
        struct {
            int   cnt[2000];
            int   off[2000];
            float dinv[2000];
            int   wsum[4];
            int   is64;
        } prep;
    } u;
    __shared__ float w1s[96 * 32];        // [(ci*3+kt)*32 + co]
    __shared__ float gws[32 * 32];        // [c2*32 + co]
    __shared__ float b1s[32];

    int tid = threadIdx.x;

    // ---------------- fused CSR preprocessing block ----------------
    if (blockIdx.x == NBLK) {
        if (blockIdx.y != 0 || blockIdx.z != 0) return;

        if (tid == 0) {
            const int* q = (const int*)edges;
            int ok = 1;
            #pragma unroll 1
            for (int i = 0; i < 64; i++) {
                if (q[2 * i + 1] != 0) { ok = 0; break; }
            }
            u.prep.is64 = ok;
        }
        for (int i = tid; i < N_; i += 128) u.prep.cnt[i] = 0;
        __syncthreads();
        const int is64 = u.prep.is64;

        // pass 1: convert + histogram
        #pragma unroll 1
        for (int e = tid; e < E_; e += 128) {
            int s, d;
            if (is64) {
                const long long* p = (const long long*)edges;
                s = (int)p[e];
                d = (int)p[E_ + e];
            } else {
                const int* p = (const int*)edges;
                s = p[e];
                d = p[E_ + e];
            }
            g_srcb[e] = s;
            g_dstb[e] = d;
            atomicAdd(&u.prep.cnt[d], 1);
        }
        __syncthreads();

        // block scan over 2000 counts (16 per thread)
        int lane = tid & 31, wid = tid >> 5;
        int base = tid * 16;
        int c[16];
        int sum = 0;
        #pragma unroll
        for (int i = 0; i < 16; i++) {
            int idx = base + i;
            c[i] = (idx < N_) ? u.prep.cnt[idx] : 0;
            sum += c[i];
        }
        int incl = sum;
        #pragma unroll
        for (int o = 1; o < 32; o <<= 1) {
            int v = __shfl_up_sync(0xffffffffu, incl, o);
            if (lane >= o) incl += v;
        }
        if (lane == 31) u.prep.wsum[wid] = incl;
        __syncthreads();
        int woff = 0;
        #pragma unroll
        for (int w = 0; w < 4; w++) woff += (w < wid) ? u.prep.wsum[w] : 0;
        int run = woff + incl - sum;
        #pragma unroll
        for (int i = 0; i < 16; i++) {
            int idx = base + i;
            if (idx < N_) {
                u.prep.off[idx] = run;
                g_off[idx] = run;
                float deg = (float)c[i] + 1.0f;
                u.prep.dinv[idx] = rsqrtf(deg);
                g_invdeg[idx] = 1.0f / deg;
            }
            run += c[i];
        }
        if (tid == 127) g_off[N_] = E_;
        __syncthreads();
        for (int i = tid; i < N_; i += 128) u.prep.cnt[i] = 0;
        __syncthreads();

        // fill
        #pragma unroll 1
        for (int e = tid; e < E_; e += 128) {
            int s = g_srcb[e];
            int d = g_dstb[e];
            int pos = atomicAdd(&u.prep.cnt[d], 1);
            int idx = u.prep.off[d] + pos;
            g_csr_src[idx] = s;
            g_csr_w[idx] = u.prep.dinv[s] * u.prep.dinv[d];
        }
        return;
    }

    // ---------------- conv1 + gcn_w GEMM ----------------
    for (int i = tid; i < 96 * 32; i += 128) {
        int co = i & 31;
        int r = i >> 5;
        int kt = r % 3;
        int ci = r / 3;
        w1s[i] = w1[(co * C_ + ci) * 3 + kt];
    }
    for (int i = tid; i < 32 * 32; i += 128) gws[i] = gcn_w[i];
    if (tid < 32) b1s[tid] = b1[tid];
    __syncthreads();

    int cog = tid & 3;
    int ptg = tid >> 2;          // 0..31
    int co0 = cog * 8;
    int n0  = blockIdx.x * PTSB;
    int nb  = n0 + ptg * 8;
    bool alive = (nb < N_);
    int t = blockIdx.y;
    int b = blockIdx.z;

    // Stage A: h = conv1(x) + b1
    unsigned long long acc[4][8];
    #pragma unroll
    for (int q = 0; q < 8; q++) {
        unsigned long long bq = dup2(b1s[co0 + q]);
        #pragma unroll
        for (int pp = 0; pp < 4; pp++) acc[pp][q] = bq;
    }

    const float* xbase = x + (size_t)(b * C_ * T_) * N_ + nb;
    #pragma unroll 1
    for (int ci = 0; ci < 32; ci++) {
        const float* xr = xbase + ci * (T_ * N_);
        #pragma unroll
        for (int kt = 0; kt < 3; kt++) {
            int tt = t + kt - 1;
            if (tt < 0 || tt >= T_) continue;
            unsigned long long in0 = 0, in1 = 0, in2v = 0, in3 = 0;
            if (alive) {
                const ulonglong2* p = (const ulonglong2*)(xr + tt * N_);
                ulonglong2 va = p[0];
                ulonglong2 vb = p[1];
                in0 = va.x; in1 = va.y; in2v = vb.x; in3 = vb.y;
            }
            const float* wr = &w1s[(ci * 3 + kt) * 32 + co0];
            float4 wA = *(const float4*)wr;
            float4 wB = *(const float4*)(wr + 4);
            unsigned long long wd[8];
            wd[0] = dup2(wA.x); wd[1] = dup2(wA.y);
            wd[2] = dup2(wA.z); wd[3] = dup2(wA.w);
            wd[4] = dup2(wB.x); wd[5] = dup2(wB.y);
            wd[6] = dup2(wB.z); wd[7] = dup2(wB.w);
            unsigned long long in2a[4] = {in0, in1, in2v, in3};
            #pragma unroll
            for (int pp = 0; pp < 4; pp++) {
                #pragma unroll
                for (int q = 0; q < 8; q++) ffma2(acc[pp][q], in2a[pp], wd[q]);
            }
        }
    }

    // relu -> htile [co][pt]
    float* htile = u.pool;
    #pragma unroll
    for (int pp = 0; pp < 4; pp++) {
        int pt = ptg * 8 + 2 * pp;
        #pragma unroll
        for (int q = 0; q < 8; q++) {
            float2 v = unpack2(acc[pp][q]);
            int co = co0 + q;
            htile[co * HSTRIDE + pt]     = fmaxf(v.x, 0.0f);
            htile[co * HSTRIDE + pt + 1] = fmaxf(v.y, 0.0f);
        }
    }
    __syncthreads();

    // Stage B: xw = h @ gcn_w
    unsigned long long xa[4][8];
    #pragma unroll
    for (int pp = 0; pp < 4; pp++)
        #pragma unroll
        for (int q = 0; q < 8; q++) xa[pp][q] = 0ull;

    #pragma unroll 1
    for (int c2 = 0; c2 < 32; c2++) {
        const ulonglong2* hp = (const ulonglong2*)&htile[c2 * HSTRIDE + ptg * 8];
        ulonglong2 va = hp[0];
        ulonglong2 vb = hp[1];
        unsigned long long in2a[4] = {va.x, va.y, vb.x, vb.y};
        const float* wr = &gws[c2 * 32 + co0];
        float4 wA = *(const float4*)wr;
        float4 wB = *(const float4*)(wr + 4);
        unsigned long long wd[8];
        wd[0] = dup2(wA.x); wd[1] = dup2(wA.y);
        wd[2] = dup2(wA.z); wd[3] = dup2(wA.w);
        wd[4] = dup2(wB.x); wd[5] = dup2(wB.y);
        wd[6] = dup2(wB.z); wd[7] = dup2(wB.w);
        #pragma unroll
        for (int pp = 0; pp < 4; pp++) {
            #pragma unroll
            for (int q = 0; q < 8; q++) ffma2(xa[pp][q], in2a[pp], wd[q]);
        }
    }
    __syncthreads();   // htile reads done before pool reuse

    // transpose to [pt][c] and store coalesced
    float* xwt = u.pool;
    #pragma unroll
    for (int pp = 0; pp < 4; pp++) {
        int pt = ptg * 8 + 2 * pp;
        #pragma unroll
        for (int q = 0; q < 8; q++) {
            float2 v = unpack2(xa[pp][q]);
            int co = co0 + q;
            xwt[pt * XWSTRIDE + co]       = v.x;
            xwt[(pt + 1) * XWSTRIDE + co] = v.y;
        }
    }
    __syncthreads();

    int g = b * T_ + t;
    float* dst = g_xw + ((size_t)g * N_ + n0) * C_;
    int rows = min(PTSB, N_ - n0);
    for (int i = tid; i < rows * C_; i += 128) {
        dst[i] = xwt[(i >> 5) * XWSTRIDE + (i & 31)];
    }
}

// ---------------------------------------------------------------------------
// K2: GCN aggregation (gather-reduce); writes g_gout transposed [g][c][n].
// ---------------------------------------------------------------------------
__global__ void __launch_bounds__(256) k_agg(const float* __restrict__ gcn_b) {
    __shared__ float sbuf[256];
    int warp = threadIdx.x >> 5;
    int lane = threadIdx.x & 31;
    int n = blockIdx.x * 8 + warp;
    int g = blockIdx.y;

    int s0 = g_off[n];
    int s1 = g_off[n + 1];
    const float* __restrict__ xwg = g_xw + (size_t)g * N_ * C_;

    float accA = 0.0f, accB = 0.0f;
    int e = s0;
    for (; e + 1 < s1; e += 2) {
        int   sA = g_csr_src[e];
        int   sB = g_csr_src[e + 1];
        float wA = g_csr_w[e];
        float wB = g_csr_w[e + 1];
        float vA = __ldg(&xwg[sA * C_ + lane]);
        float vB = __ldg(&xwg[sB * C_ + lane]);
        accA += wA * vA;
        accB += wB * vB;
    }
    if (e < s1) {
        accA += g_csr_w[e] * __ldg(&xwg[g_csr_src[e] * C_ + lane]);
    }
    float acc = accA + accB + g_invdeg[n] * xwg[n * C_ + lane] + gcn_b[lane];

    sbuf[lane * 8 + warp] = acc;
    __syncthreads();
    int c = threadIdx.x >> 3;
    int j = threadIdx.x & 7;
    g_gout[((size_t)g * C_ + c) * N_ + blockIdx.x * 8 + j] = sbuf[c * 8 + j];
}

// ---------------------------------------------------------------------------
// K3: conv2, register-blocked GEMM; direct coalesced LDG from g_gout [g][c][n].
// ---------------------------------------------------------------------------
__global__ void __launch_bounds__(128) k_conv2(
    const float* __restrict__ w2,
    const float* __restrict__ b2,
    float* __restrict__ out)
{
    __shared__ float w2s[96 * 32];   // [(ci*3+kt)*32 + co]
    __shared__ float b2s[32];

    int tid = threadIdx.x;
    for (int i = tid; i < 96 * 32; i += 128) {
        int co = i & 31;
        int r = i >> 5;
        int kt = r % 3;
        int ci = r / 3;
        w2s[i] = w2[(co * C_ + ci) * 3 + kt];
    }
    if (tid < 32) b2s[tid] = b2[tid];
    __syncthreads();

    int cog = tid & 3;
    int ptg = tid >> 2;
    int co0 = cog * 8;
    int n0  = blockIdx.x * PTSB;
    int nb  = n0 + ptg * 8;
    bool alive = (nb < N_);
    int t = blockIdx.y;
    int b = blockIdx.z;

    unsigned long long acc[4][8];
    #pragma unroll
    for (int q = 0; q < 8; q++) {
        unsigned long long bq = dup2(b2s[co0 + q]);
        #pragma unroll
        for (int pp = 0; pp < 4; pp++) acc[pp][q] = bq;
    }

    const float* gbase = g_gout + (size_t)(b * T_) * C_ * N_ + nb;
    #pragma unroll 1
    for (int ci = 0; ci < 32; ci++) {
        #pragma unroll
        for (int kt = 0; kt < 3; kt++) {
            int tt = t + kt - 1;
            if (tt < 0 || tt >= T_) continue;
            unsigned long long in0 = 0, in1 = 0, in2v = 0, in3 = 0;
            if (alive) {
                const ulonglong2* p =
                    (const ulonglong2*)(gbase + (size_t)(tt * C_ + ci) * N_);
                ulonglong2 va = p[0];
                ulonglong2 vb = p[1];
                in0 = va.x; in1 = va.y; in2v = vb.x; in3 = vb.y;
            }
            const float* wr = &w2s[(ci * 3 + kt) * 32 + co0];
            float4 wA = *(const float4*)wr;
            float4 wB = *(const float4*)(wr + 4);
            unsigned long long wd[8];
            wd[0] = dup2(wA.x); wd[1] = dup2(wA.y);
            wd[2] = dup2(wA.z); wd[3] = dup2(wA.w);
            wd[4] = dup2(wB.x); wd[5] = dup2(wB.y);
            wd[6] = dup2(wB.z); wd[7] = dup2(wB.w);
            unsigned long long in2a[4] = {in0, in1, in2v, in3};
            #pragma unroll
            for (int pp = 0; pp < 4; pp++) {
                #pragma unroll
                for (int q = 0; q < 8; q++) ffma2(acc[pp][q], in2a[pp], wd[q]);
            }
        }
    }

    if (alive) {
        #pragma unroll
        for (int q = 0; q < 8; q++) {
            int co = co0 + q;
            float* orow = out + ((size_t)(b * C_ + co) * T_ + t) * N_ + nb;
            #pragma unroll
            for (int pp = 0; pp < 4; pp++) {
                float2 v = unpack2(acc[pp][q]);
                *(float2*)(orow + 2 * pp) = v;
            }
        }
    }
}

// ---------------------------------------------------------------------------
// Launcher
// ---------------------------------------------------------------------------
extern "C" void kernel_launch(void* const* d_in, const int* in_sizes, int n_in,
                              void* d_out, int out_size) {
    const float* x     = (const float*)d_in[0];
    const void*  edges = d_in[1];
    const float* w1    = (const float*)d_in[2];
    const float* b1    = (const float*)d_in[3];
    const float* gcn_w = (const float*)d_in[4];
    const float* gcn_b = (const float*)d_in[5];
    const float* w2    = (const float*)d_in[6];
    const float* b2    = (const float*)d_in[7];
    float* out = (float*)d_out;

    dim3 g1(NBLK + 1, T_, B_);       // +1 block does CSR preprocessing
    k_conv1<<<g1, 128>>>(x, edges, w1, b1, gcn_w);

    dim3 ga(N_ / 8, BT_);
    k_agg<<<ga, 256>>>(gcn_b);

    dim3 g2(NBLK, T_, B_);
    k_conv2<<<g2, 128>>>(w2, b2, out);
}

// round 8
// speedup vs baseline: 1.3131x; 1.1673x over previous
#include <cuda_runtime.h>
#include <math.h>

// Problem constants (fixed shapes)
#define B_  4
#define C_  32
#define T_  48
#define N_  2000
#define E_  16000
#define BT_ (B_ * T_)   // 192

#define PTSB 256        // points per conv block
#define NBLK 8          // ceil(2000/256)
#define HSTRIDE 264     // htile row stride (words)
#define XWSTRIDE 34     // xw transpose tile row stride (words, EVEN for ST.64)

typedef unsigned long long ull;

// ---------------------------------------------------------------------------
// Scratch (device globals)
// ---------------------------------------------------------------------------
__device__ float g_xw[BT_ * N_ * C_];     // [g][n][c] (for gather)
__device__ float g_gout[BT_ * C_ * N_];   // [g][c][n] (for conv2 coalesced reads)
__device__ int   g_srcb[E_];
__device__ int   g_dstb[E_];
__device__ int   g_off[N_ + 1];
__device__ int   g_csr_src[E_];
__device__ float g_csr_w[E_];
__device__ float g_invdeg[N_];

// ---------------------------------------------------------------------------
// f32x2 helpers
// ---------------------------------------------------------------------------
__device__ __forceinline__ ull dup2(float x) {
    ull r;
    unsigned u = __float_as_uint(x);
    asm("mov.b64 %0, {%1, %1};" : "=l"(r) : "r"(u));
    return r;
}
__device__ __forceinline__ void ffma2(ull& acc, ull a, ull b) {
    asm("fma.rn.f32x2 %0, %1, %2, %0;" : "+l"(acc) : "l"(a), "l"(b));
}
__device__ __forceinline__ float2 unpack2(ull v) {
    unsigned lo, hi;
    asm("mov.b64 {%0, %1}, %2;" : "=r"(lo), "=r"(hi) : "l"(v));
    return make_float2(__uint_as_float(lo), __uint_as_float(hi));
}

// ---------------------------------------------------------------------------
// K1: fused conv1+relu+gcn_w GEMM (256 threads), with CSR preprocessing
// fused in as one extra block (blockIdx.x == NBLK).
// Thread map: cog = tid&3 (co0 = cog*8), ptg = tid>>2 (4 points each).
// acc[pt][cp]: f32x2 packing channel pair (co0+2cp, co0+2cp+1).
// ---------------------------------------------------------------------------
__global__ void __launch_bounds__(256, 4) k_conv1(
    const float* __restrict__ x,
    const void*  __restrict__ edges,
    const float* __restrict__ w1,
    const float* __restrict__ b1,
    const float* __restrict__ gcn_w)
{
    __shared__ __align__(16) union U {
        float pool[8704];                 // htile [32][264] / xwtile [256][34]
        struct {
            int   cnt[2000];
            int   off[2000];
            float dinv[2000];
            int   wsum[8];
            int   is64;
        } prep;
    } u;
    __shared__ __align__(16) float w1s[96 * 32];   // [(ci*3+kt)*32 + co]
    __shared__ __align__(16) float gws[32 * 32];   // [c2*32 + co]
    __shared__ __align__(16) float b1s[32];

    int tid = threadIdx.x;

    // ---------------- fused CSR preprocessing block ----------------
    if (blockIdx.x == NBLK) {
        if (blockIdx.y != 0 || blockIdx.z != 0) return;

        if (tid == 0) {
            const int* q = (const int*)edges;
            int ok = 1;
            #pragma unroll 1
            for (int i = 0; i < 64; i++) {
                if (q[2 * i + 1] != 0) { ok = 0; break; }
            }
            u.prep.is64 = ok;
        }
        for (int i = tid; i < N_; i += 256) u.prep.cnt[i] = 0;
        __syncthreads();
        const int is64 = u.prep.is64;

        #pragma unroll 1
        for (int e = tid; e < E_; e += 256) {
            int s, d;
            if (is64) {
                const long long* p = (const long long*)edges;
                s = (int)p[e];
                d = (int)p[E_ + e];
            } else {
                const int* p = (const int*)edges;
                s = p[e];
                d = p[E_ + e];
            }
            g_srcb[e] = s;
            g_dstb[e] = d;
            atomicAdd(&u.prep.cnt[d], 1);
        }
        __syncthreads();

        // block scan over 2000 counts (8 per thread, 256 threads)
        int lane = tid & 31, wid = tid >> 5;
        int base = tid * 8;
        int c[8];
        int sum = 0;
        #pragma unroll
        for (int i = 0; i < 8; i++) {
            int idx = base + i;
            c[i] = (idx < N_) ? u.prep.cnt[idx] : 0;
            sum += c[i];
        }
        int incl = sum;
        #pragma unroll
        for (int o = 1; o < 32; o <<= 1) {
            int v = __shfl_up_sync(0xffffffffu, incl, o);
            if (lane >= o) incl += v;
        }
        if (lane == 31) u.prep.wsum[wid] = incl;
        __syncthreads();
        int woff = 0;
        #pragma unroll
        for (int w = 0; w < 8; w++) woff += (w < wid) ? u.prep.wsum[w] : 0;
        int run = woff + incl - sum;
        #pragma unroll
        for (int i = 0; i < 8; i++) {
            int idx = base + i;
            if (idx < N_) {
                u.prep.off[idx] = run;
                g_off[idx] = run;
                float deg = (float)c[i] + 1.0f;
                u.prep.dinv[idx] = rsqrtf(deg);
                g_invdeg[idx] = 1.0f / deg;
            }
            run += c[i];
        }
        if (tid == 0) g_off[N_] = E_;
        __syncthreads();
        for (int i = tid; i < N_; i += 256) u.prep.cnt[i] = 0;
        __syncthreads();

        #pragma unroll 1
        for (int e = tid; e < E_; e += 256) {
            int s = g_srcb[e];
            int d = g_dstb[e];
            int pos = atomicAdd(&u.prep.cnt[d], 1);
            int idx = u.prep.off[d] + pos;
            g_csr_src[idx] = s;
            g_csr_w[idx] = u.prep.dinv[s] * u.prep.dinv[d];
        }
        return;
    }

    // ---------------- conv1 + gcn_w GEMM ----------------
    for (int i = tid; i < 96 * 32; i += 256) {
        int co = i & 31;
        int r = i >> 5;
        int kt = r % 3;
        int ci = r / 3;
        w1s[i] = w1[(co * C_ + ci) * 3 + kt];
    }
    for (int i = tid; i < 32 * 32; i += 256) gws[i] = gcn_w[i];
    if (tid < 32) b1s[tid] = b1[tid];
    __syncthreads();

    int cog = tid & 3;
    int ptg = tid >> 2;              // 0..63
    int co0 = cog * 8;
    int n0  = blockIdx.x * PTSB;
    int nb  = n0 + ptg * 4;
    bool alive = (nb < N_);
    int t = blockIdx.y;
    int b = blockIdx.z;

    // Stage A: h = conv1(x) + b1
    ull acc[4][4];
    {
        const ull* bp = (const ull*)b1s;   // pairs (2c, 2c+1)
        #pragma unroll
        for (int cp = 0; cp < 4; cp++) {
            ull bq = bp[co0 / 2 + cp];
            #pragma unroll
            for (int pt = 0; pt < 4; pt++) acc[pt][cp] = bq;
        }
    }

    const float* xbase = x + (size_t)(b * C_ * T_) * N_ + nb;
    #pragma unroll 1
    for (int ci = 0; ci < 32; ci++) {
        const float* xr = xbase + ci * (T_ * N_);
        #pragma unroll
        for (int kt = 0; kt < 3; kt++) {
            int tt = t + kt - 1;
            if (tt < 0 || tt >= T_) continue;
            float4 xv = make_float4(0.f, 0.f, 0.f, 0.f);
            if (alive) xv = *(const float4*)(xr + tt * N_);
            ull in[4];
            in[0] = dup2(xv.x); in[1] = dup2(xv.y);
            in[2] = dup2(xv.z); in[3] = dup2(xv.w);
            const ulonglong2* wp = (const ulonglong2*)&w1s[(ci * 3 + kt) * 32 + co0];
            ulonglong2 wa = wp[0];
            ulonglong2 wb = wp[1];
            #pragma unroll
            for (int pt = 0; pt < 4; pt++) {
                ffma2(acc[pt][0], in[pt], wa.x);
                ffma2(acc[pt][1], in[pt], wa.y);
                ffma2(acc[pt][2], in[pt], wb.x);
                ffma2(acc[pt][3], in[pt], wb.y);
            }
        }
    }

    // relu -> htile [co][pt]
    float* htile = u.pool;
    int pl = ptg * 4;
    #pragma unroll
    for (int pt = 0; pt < 4; pt++) {
        #pragma unroll
        for (int cp = 0; cp < 4; cp++) {
            float2 v = unpack2(acc[pt][cp]);
            htile[(co0 + 2 * cp) * HSTRIDE + pl + pt]     = fmaxf(v.x, 0.0f);
            htile[(co0 + 2 * cp + 1) * HSTRIDE + pl + pt] = fmaxf(v.y, 0.0f);
        }
    }
    __syncthreads();

    // Stage B: xw = h @ gcn_w
    ull xa[4][4];
    #pragma unroll
    for (int pt = 0; pt < 4; pt++)
        #pragma unroll
        for (int cp = 0; cp < 4; cp++) xa[pt][cp] = 0ull;

    #pragma unroll 1
    for (int c2 = 0; c2 < 32; c2++) {
        float4 hv = *(const float4*)&htile[c2 * HSTRIDE + pl];
        ull in[4];
        in[0] = dup2(hv.x); in[1] = dup2(hv.y);
        in[2] = dup2(hv.z); in[3] = dup2(hv.w);
        const ulonglong2* wp = (const ulonglong2*)&gws[c2 * 32 + co0];
        ulonglong2 wa = wp[0];
        ulonglong2 wb = wp[1];
        #pragma unroll
        for (int pt = 0; pt < 4; pt++) {
            ffma2(xa[pt][0], in[pt], wa.x);
            ffma2(xa[pt][1], in[pt], wa.y);
            ffma2(xa[pt][2], in[pt], wb.x);
            ffma2(xa[pt][3], in[pt], wb.y);
        }
    }
    __syncthreads();   // htile reads done before pool reuse

    // transpose to [pt][co] and store coalesced (XWSTRIDE even -> ST.64 ok)
    float* xwt = u.pool;
    #pragma unroll
    for (int pt = 0; pt < 4; pt++) {
        #pragma unroll
        for (int cp = 0; cp < 4; cp++) {
            float2 v = unpack2(xa[pt][cp]);
            *(float2*)&xwt[(pl + pt) * XWSTRIDE + co0 + 2 * cp] = v;
        }
    }
    __syncthreads();

    int g = b * T_ + t;
    float* dst = g_xw + ((size_t)g * N_ + n0) * C_;
    int rows = min(PTSB, N_ - n0);
    for (int i = tid; i < rows * C_; i += 256) {
        dst[i] = xwt[(i >> 5) * XWSTRIDE + (i & 31)];
    }
}

// ---------------------------------------------------------------------------
// K2: GCN aggregation; 4 graphs per warp (CSR loads amortized, MLP=4+).
// Writes g_gout transposed [g][c][n].
// ---------------------------------------------------------------------------
__global__ void __launch_bounds__(256) k_agg(const float* __restrict__ gcn_b) {
    __shared__ __align__(16) float sbuf[4 * 256];   // [gg][lane*8+warp]
    int warp = threadIdx.x >> 5;
    int lane = threadIdx.x & 31;
    int n  = blockIdx.x * 8 + warp;
    int g0 = blockIdx.y * 4;

    int s0 = g_off[n];
    int s1 = g_off[n + 1];
    const float* __restrict__ xw0 = g_xw + (size_t)g0 * N_ * C_;
    const size_t GS = (size_t)N_ * C_;

    float acc[4] = {0.f, 0.f, 0.f, 0.f};
    int e = s0;
    for (; e + 1 < s1; e += 2) {
        int   sA = g_csr_src[e];
        int   sB = g_csr_src[e + 1];
        float wA = g_csr_w[e];
        float wB = g_csr_w[e + 1];
        float vA[4], vB[4];
        #pragma unroll
        for (int gg = 0; gg < 4; gg++) vA[gg] = __ldg(&xw0[gg * GS + sA * C_ + lane]);
        #pragma unroll
        for (int gg = 0; gg < 4; gg++) vB[gg] = __ldg(&xw0[gg * GS + sB * C_ + lane]);
        #pragma unroll
        for (int gg = 0; gg < 4; gg++) acc[gg] += wA * vA[gg] + wB * vB[gg];
    }
    if (e < s1) {
        int   sA = g_csr_src[e];
        float wA = g_csr_w[e];
        #pragma unroll
        for (int gg = 0; gg < 4; gg++) acc[gg] += wA * __ldg(&xw0[gg * GS + sA * C_ + lane]);
    }
    float idg = g_invdeg[n];
    float bia = gcn_b[lane];
    #pragma unroll
    for (int gg = 0; gg < 4; gg++) {
        acc[gg] += idg * xw0[gg * GS + n * C_ + lane] + bia;
        sbuf[gg * 256 + lane * 8 + warp] = acc[gg];
    }
    __syncthreads();

    // transposed store: [g][c][n0..n0+7]
    int n0 = blockIdx.x * 8;
    #pragma unroll
    for (int r = 0; r < 4; r++) {
        int idx = r * 256 + threadIdx.x;
        int gg = idx >> 8;
        int c  = (idx >> 3) & 31;
        int j  = idx & 7;
        g_gout[((size_t)(g0 + gg) * C_ + c) * N_ + n0 + j] = sbuf[gg * 256 + c * 8 + j];
    }
}

// ---------------------------------------------------------------------------
// K3: conv2 (256 threads, co-pair packing); direct coalesced LDG from
// g_gout [g][c][n]; per-co float4 STG.128 output.
// ---------------------------------------------------------------------------
__global__ void __launch_bounds__(256, 4) k_conv2(
    const float* __restrict__ w2,
    const float* __restrict__ b2,
    float* __restrict__ out)
{
    __shared__ __align__(16) float w2s[96 * 32];   // [(ci*3+kt)*32 + co]
    __shared__ __align__(16) float b2s[32];

    int tid = threadIdx.x;
    for (int i = tid; i < 96 * 32; i += 256) {
        int co = i & 31;
        int r = i >> 5;
        int kt = r % 3;
        int ci = r / 3;
        w2s[i] = w2[(co * C_ + ci) * 3 + kt];
    }
    if (tid < 32) b2s[tid] = b2[tid];
    __syncthreads();

    int cog = tid & 3;
    int ptg = tid >> 2;
    int co0 = cog * 8;
    int n0  = blockIdx.x * PTSB;
    int nb  = n0 + ptg * 4;
    bool alive = (nb < N_);
    int t = blockIdx.y;
    int b = blockIdx.z;

    ull acc[4][4];
    {
        const ull* bp = (const ull*)b2s;
        #pragma unroll
        for (int cp = 0; cp < 4; cp++) {
            ull bq = bp[co0 / 2 + cp];
            #pragma unroll
            for (int pt = 0; pt < 4; pt++) acc[pt][cp] = bq;
        }
    }

    const float* gbase = g_gout + (size_t)(b * T_) * C_ * N_ + nb;
    #pragma unroll 1
    for (int ci = 0; ci < 32; ci++) {
        #pragma unroll
        for (int kt = 0; kt < 3; kt++) {
            int tt = t + kt - 1;
            if (tt < 0 || tt >= T_) continue;
            float4 gv = make_float4(0.f, 0.f, 0.f, 0.f);
            if (alive) gv = *(const float4*)(gbase + (size_t)(tt * C_ + ci) * N_);
            ull in[4];
            in[0] = dup2(gv.x); in[1] = dup2(gv.y);
            in[2] = dup2(gv.z); in[3] = dup2(gv.w);
            const ulonglong2* wp = (const ulonglong2*)&w2s[(ci * 3 + kt) * 32 + co0];
            ulonglong2 wa = wp[0];
            ulonglong2 wb = wp[1];
            #pragma unroll
            for (int pt = 0; pt < 4; pt++) {
                ffma2(acc[pt][0], in[pt], wa.x);
                ffma2(acc[pt][1], in[pt], wa.y);
                ffma2(acc[pt][2], in[pt], wb.x);
                ffma2(acc[pt][3], in[pt], wb.y);
            }
        }
    }

    if (alive) {
        #pragma unroll
        for (int cp = 0; cp < 4; cp++) {
            float2 v0 = unpack2(acc[0][cp]);
            float2 v1 = unpack2(acc[1][cp]);
            float2 v2 = unpack2(acc[2][cp]);
            float2 v3 = unpack2(acc[3][cp]);
            int coA = co0 + 2 * cp;
            int coB = coA + 1;
            float4 lo = make_float4(v0.x, v1.x, v2.x, v3.x);
            float4 hi = make_float4(v0.y, v1.y, v2.y, v3.y);
            *(float4*)(out + ((size_t)(b * C_ + coA) * T_ + t) * N_ + nb) = lo;
            *(float4*)(out + ((size_t)(b * C_ + coB) * T_ + t) * N_ + nb) = hi;
        }
    }
}

// ---------------------------------------------------------------------------
// Launcher
// ---------------------------------------------------------------------------
extern "C" void kernel_launch(void* const* d_in, const int* in_sizes, int n_in,
                              void* d_out, int out_size) {
    const float* x     = (const float*)d_in[0];
    const void*  edges = d_in[1];
    const float* w1    = (const float*)d_in[2];
    const float* b1    = (const float*)d_in[3];
    const float* gcn_w = (const float*)d_in[4];
    const float* gcn_b = (const float*)d_in[5];
    const float* w2    = (const float*)d_in[6];
    const float* b2    = (const float*)d_in[7];
    float* out = (float*)d_out;

    dim3 g1(NBLK + 1, T_, B_);       // +1 block does CSR preprocessing
    k_conv1<<<g1, 256>>>(x, edges, w1, b1, gcn_w);

    dim3 ga(N_ / 8, BT_ / 4);
    k_agg<<<ga, 256>>>(gcn_b);

    dim3 g2(NBLK, T_, B_);
    k_conv2<<<g2, 256>>>(w2, b2, out);
}

// round 9
// speedup vs baseline: 1.3233x; 1.0078x over previous
#include <cuda_runtime.h>
#include <math.h>

// Problem constants (fixed shapes)
#define B_  4
#define C_  32
#define T_  48
#define N_  2000
#define E_  16000
#define BT_ (B_ * T_)   // 192

#define PTSB 256        // points per conv block
#define NBLK 8          // ceil(2000/256)
#define HSTRIDE 264     // htile row stride (words)
#define XWSTRIDE 34     // xw transpose tile row stride (words, EVEN for ST.64)

typedef unsigned long long ull;

// ---------------------------------------------------------------------------
// Scratch (device globals)
// ---------------------------------------------------------------------------
__device__ float g_xw[BT_ * N_ * C_];     // [g][n][c] (for gather)
__device__ float g_gout[BT_ * C_ * N_];   // [g][c][n] (for conv2 coalesced reads)
__device__ int   g_srcb[E_];
__device__ int   g_dstb[E_];
__device__ int   g_off[N_ + 1];
__device__ int   g_csr_src[E_];
__device__ float g_csr_w[E_];
__device__ float g_invdeg[N_];

// ---------------------------------------------------------------------------
// f32x2 helpers
// ---------------------------------------------------------------------------
__device__ __forceinline__ ull dup2(float x) {
    ull r;
    unsigned u = __float_as_uint(x);
    asm("mov.b64 %0, {%1, %1};" : "=l"(r) : "r"(u));
    return r;
}
__device__ __forceinline__ void ffma2(ull& acc, ull a, ull b) {
    asm("fma.rn.f32x2 %0, %1, %2, %0;" : "+l"(acc) : "l"(a), "l"(b));
}
__device__ __forceinline__ float2 unpack2(ull v) {
    unsigned lo, hi;
    asm("mov.b64 {%0, %1}, %2;" : "=r"(lo), "=r"(hi) : "l"(v));
    return make_float2(__uint_as_float(lo), __uint_as_float(hi));
}

// ---------------------------------------------------------------------------
// K1: fused conv1+relu+gcn_w GEMM (256 threads), with CSR preprocessing
// fused in as one extra block (blockIdx.x == NBLK).
// Thread map: cog = tid&3 (co0 = cog*8), ptg = tid>>2 (4 points each).
// acc[pt][cp]: f32x2 packing channel pair (co0+2cp, co0+2cp+1).
// ---------------------------------------------------------------------------
__global__ void __launch_bounds__(256, 4) k_conv1(
    const float* __restrict__ x,
    const void*  __restrict__ edges,
    const float* __restrict__ w1,
    const float* __restrict__ b1,
    const float* __restrict__ gcn_w)
{
    __shared__ __align__(16) union U {
        float pool[8704];                 // htile [32][264] / xwtile [256][34]
        struct {
            int   cnt[2000];
            int   off[2000];
            float dinv[2000];
            int   wsum[8];
            int   is64;
        } prep;
    } u;
    __shared__ __align__(16) float w1s[96 * 32];   // [(ci*3+kt)*32 + co]
    __shared__ __align__(16) float gws[32 * 32];   // [c2*32 + co]
    __shared__ __align__(16) float b1s[32];

    int tid = threadIdx.x;

    // ---------------- fused CSR preprocessing block ----------------
    if (blockIdx.x == NBLK) {
        if (blockIdx.y != 0 || blockIdx.z != 0) return;

        if (tid == 0) {
            const int* q = (const int*)edges;
            int ok = 1;
            #pragma unroll 1
            for (int i = 0; i < 64; i++) {
                if (q[2 * i + 1] != 0) { ok = 0; break; }
            }
            u.prep.is64 = ok;
        }
        for (int i = tid; i < N_; i += 256) u.prep.cnt[i] = 0;
        __syncthreads();
        const int is64 = u.prep.is64;

        #pragma unroll 1
        for (int e = tid; e < E_; e += 256) {
            int s, d;
            if (is64) {
                const long long* p = (const long long*)edges;
                s = (int)p[e];
                d = (int)p[E_ + e];
            } else {
                const int* p = (const int*)edges;
                s = p[e];
                d = p[E_ + e];
            }
            g_srcb[e] = s;
            g_dstb[e] = d;
            atomicAdd(&u.prep.cnt[d], 1);
        }
        __syncthreads();

        // block scan over 2000 counts (8 per thread, 256 threads)
        int lane = tid & 31, wid = tid >> 5;
        int base = tid * 8;
        int c[8];
        int sum = 0;
        #pragma unroll
        for (int i = 0; i < 8; i++) {
            int idx = base + i;
            c[i] = (idx < N_) ? u.prep.cnt[idx] : 0;
            sum += c[i];
        }
        int incl = sum;
        #pragma unroll
        for (int o = 1; o < 32; o <<= 1) {
            int v = __shfl_up_sync(0xffffffffu, incl, o);
            if (lane >= o) incl += v;
        }
        if (lane == 31) u.prep.wsum[wid] = incl;
        __syncthreads();
        int woff = 0;
        #pragma unroll
        for (int w = 0; w < 8; w++) woff += (w < wid) ? u.prep.wsum[w] : 0;
        int run = woff + incl - sum;
        #pragma unroll
        for (int i = 0; i < 8; i++) {
            int idx = base + i;
            if (idx < N_) {
                u.prep.off[idx] = run;
                g_off[idx] = run;
                float deg = (float)c[i] + 1.0f;
                u.prep.dinv[idx] = rsqrtf(deg);
                g_invdeg[idx] = 1.0f / deg;
            }
            run += c[i];
        }
        if (tid == 0) g_off[N_] = E_;
        __syncthreads();
        for (int i = tid; i < N_; i += 256) u.prep.cnt[i] = 0;
        __syncthreads();

        #pragma unroll 1
        for (int e = tid; e < E_; e += 256) {
            int s = g_srcb[e];
            int d = g_dstb[e];
            int pos = atomicAdd(&u.prep.cnt[d], 1);
            int idx = u.prep.off[d] + pos;
            g_csr_src[idx] = s;
            g_csr_w[idx] = u.prep.dinv[s] * u.prep.dinv[d];
        }
        return;
    }

    // ---------------- conv1 + gcn_w GEMM ----------------
    for (int i = tid; i < 96 * 32; i += 256) {
        int co = i & 31;
        int r = i >> 5;
        int kt = r % 3;
        int ci = r / 3;
        w1s[i] = w1[(co * C_ + ci) * 3 + kt];
    }
    for (int i = tid; i < 32 * 32; i += 256) gws[i] = gcn_w[i];
    if (tid < 32) b1s[tid] = b1[tid];
    __syncthreads();

    int cog = tid & 3;
    int ptg = tid >> 2;              // 0..63
    int co0 = cog * 8;
    int n0  = blockIdx.x * PTSB;
    int nb  = n0 + ptg * 4;
    bool alive = (nb < N_);
    int t = blockIdx.y;
    int b = blockIdx.z;

    // Stage A: h = conv1(x) + b1
    ull acc[4][4];
    {
        const ull* bp = (const ull*)b1s;   // pairs (2c, 2c+1)
        #pragma unroll
        for (int cp = 0; cp < 4; cp++) {
            ull bq = bp[co0 / 2 + cp];
            #pragma unroll
            for (int pt = 0; pt < 4; pt++) acc[pt][cp] = bq;
        }
    }

    const float* xbase = x + (size_t)(b * C_ * T_) * N_ + nb;
    #pragma unroll 2
    for (int ci = 0; ci < 32; ci++) {
        const float* xr = xbase + ci * (T_ * N_);
        #pragma unroll
        for (int kt = 0; kt < 3; kt++) {
            int tt = t + kt - 1;
            if (tt < 0 || tt >= T_) continue;
            float4 xv = make_float4(0.f, 0.f, 0.f, 0.f);
            if (alive) xv = *(const float4*)(xr + tt * N_);
            ull in[4];
            in[0] = dup2(xv.x); in[1] = dup2(xv.y);
            in[2] = dup2(xv.z); in[3] = dup2(xv.w);
            const ulonglong2* wp = (const ulonglong2*)&w1s[(ci * 3 + kt) * 32 + co0];
            ulonglong2 wa = wp[0];
            ulonglong2 wb = wp[1];
            #pragma unroll
            for (int pt = 0; pt < 4; pt++) {
                ffma2(acc[pt][0], in[pt], wa.x);
                ffma2(acc[pt][1], in[pt], wa.y);
                ffma2(acc[pt][2], in[pt], wb.x);
                ffma2(acc[pt][3], in[pt], wb.y);
            }
        }
    }

    // relu -> htile [co][pt]
    float* htile = u.pool;
    int pl = ptg * 4;
    #pragma unroll
    for (int pt = 0; pt < 4; pt++) {
        #pragma unroll
        for (int cp = 0; cp < 4; cp++) {
            float2 v = unpack2(acc[pt][cp]);
            htile[(co0 + 2 * cp) * HSTRIDE + pl + pt]     = fmaxf(v.x, 0.0f);
            htile[(co0 + 2 * cp + 1) * HSTRIDE + pl + pt] = fmaxf(v.y, 0.0f);
        }
    }
    __syncthreads();

    // Stage B: xw = h @ gcn_w
    ull xa[4][4];
    #pragma unroll
    for (int pt = 0; pt < 4; pt++)
        #pragma unroll
        for (int cp = 0; cp < 4; cp++) xa[pt][cp] = 0ull;

    #pragma unroll 4
    for (int c2 = 0; c2 < 32; c2++) {
        float4 hv = *(const float4*)&htile[c2 * HSTRIDE + pl];
        ull in[4];
        in[0] = dup2(hv.x); in[1] = dup2(hv.y);
        in[2] = dup2(hv.z); in[3] = dup2(hv.w);
        const ulonglong2* wp = (const ulonglong2*)&gws[c2 * 32 + co0];
        ulonglong2 wa = wp[0];
        ulonglong2 wb = wp[1];
        #pragma unroll
        for (int pt = 0; pt < 4; pt++) {
            ffma2(xa[pt][0], in[pt], wa.x);
            ffma2(xa[pt][1], in[pt], wa.y);
            ffma2(xa[pt][2], in[pt], wb.x);
            ffma2(xa[pt][3], in[pt], wb.y);
        }
    }
    __syncthreads();   // htile reads done before pool reuse

    // transpose to [pt][co] and store coalesced (XWSTRIDE even -> ST.64 ok)
    float* xwt = u.pool;
    #pragma unroll
    for (int pt = 0; pt < 4; pt++) {
        #pragma unroll
        for (int cp = 0; cp < 4; cp++) {
            float2 v = unpack2(xa[pt][cp]);
            *(float2*)&xwt[(pl + pt) * XWSTRIDE + co0 + 2 * cp] = v;
        }
    }
    __syncthreads();

    int g = b * T_ + t;
    float* dst = g_xw + ((size_t)g * N_ + n0) * C_;
    int rows = min(PTSB, N_ - n0);
    for (int i = tid; i < rows * C_; i += 256) {
        dst[i] = xwt[(i >> 5) * XWSTRIDE + (i & 31)];
    }
}

// ---------------------------------------------------------------------------
// K2: GCN aggregation; 4 graphs per warp (CSR loads amortized, MLP=8).
// Writes g_gout transposed [g][c][n].
// ---------------------------------------------------------------------------
__global__ void __launch_bounds__(256) k_agg(const float* __restrict__ gcn_b) {
    __shared__ __align__(16) float sbuf[4 * 256];   // [gg][lane*8+warp]
    int warp = threadIdx.x >> 5;
    int lane = threadIdx.x & 31;
    int n  = blockIdx.x * 8 + warp;
    int g0 = blockIdx.y * 4;

    int s0 = g_off[n];
    int s1 = g_off[n + 1];
    const float* __restrict__ xw0 = g_xw + (size_t)g0 * N_ * C_;
    const size_t GS = (size_t)N_ * C_;

    float acc[4] = {0.f, 0.f, 0.f, 0.f};
    int e = s0;
    for (; e + 1 < s1; e += 2) {
        int   sA = g_csr_src[e];
        int   sB = g_csr_src[e + 1];
        float wA = g_csr_w[e];
        float wB = g_csr_w[e + 1];
        float vA[4], vB[4];
        #pragma unroll
        for (int gg = 0; gg < 4; gg++) vA[gg] = __ldg(&xw0[gg * GS + sA * C_ + lane]);
        #pragma unroll
        for (int gg = 0; gg < 4; gg++) vB[gg] = __ldg(&xw0[gg * GS + sB * C_ + lane]);
        #pragma unroll
        for (int gg = 0; gg < 4; gg++) acc[gg] += wA * vA[gg] + wB * vB[gg];
    }
    if (e < s1) {
        int   sA = g_csr_src[e];
        float wA = g_csr_w[e];
        #pragma unroll
        for (int gg = 0; gg < 4; gg++) acc[gg] += wA * __ldg(&xw0[gg * GS + sA * C_ + lane]);
    }
    float idg = g_invdeg[n];
    float bia = gcn_b[lane];
    #pragma unroll
    for (int gg = 0; gg < 4; gg++) {
        acc[gg] += idg * xw0[gg * GS + n * C_ + lane] + bia;
        sbuf[gg * 256 + lane * 8 + warp] = acc[gg];
    }
    __syncthreads();

    // transposed store: [g][c][n0..n0+7]
    int n0 = blockIdx.x * 8;
    #pragma unroll
    for (int r = 0; r < 4; r++) {
        int idx = r * 256 + threadIdx.x;
        int gg = idx >> 8;
        int c  = (idx >> 3) & 31;
        int j  = idx & 7;
        g_gout[((size_t)(g0 + gg) * C_ + c) * N_ + n0 + j] = sbuf[gg * 256 + c * 8 + j];
    }
}

// ---------------------------------------------------------------------------
// K3: conv2 (256 threads, co-pair packing); direct coalesced LDG from
// g_gout [g][c][n]; per-co float4 STG.128 output.
// ---------------------------------------------------------------------------
__global__ void __launch_bounds__(256, 4) k_conv2(
    const float* __restrict__ w2,
    const float* __restrict__ b2,
    float* __restrict__ out)
{
    __shared__ __align__(16) float w2s[96 * 32];   // [(ci*3+kt)*32 + co]
    __shared__ __align__(16) float b2s[32];

    int tid = threadIdx.x;
    for (int i = tid; i < 96 * 32; i += 256) {
        int co = i & 31;
        int r = i >> 5;
        int kt = r % 3;
        int ci = r / 3;
        w2s[i] = w2[(co * C_ + ci) * 3 + kt];
    }
    if (tid < 32) b2s[tid] = b2[tid];
    __syncthreads();

    int cog = tid & 3;
    int ptg = tid >> 2;
    int co0 = cog * 8;
    int n0  = blockIdx.x * PTSB;
    int nb  = n0 + ptg * 4;
    bool alive = (nb < N_);
    int t = blockIdx.y;
    int b = blockIdx.z;

    ull acc[4][4];
    {
        const ull* bp = (const ull*)b2s;
        #pragma unroll
        for (int cp = 0; cp < 4; cp++) {
            ull bq = bp[co0 / 2 + cp];
            #pragma unroll
            for (int pt = 0; pt < 4; pt++) acc[pt][cp] = bq;
        }
    }

    const float* gbase = g_gout + (size_t)(b * T_) * C_ * N_ + nb;
    #pragma unroll 2
    for (int ci = 0; ci < 32; ci++) {
        #pragma unroll
        for (int kt = 0; kt < 3; kt++) {
            int tt = t + kt - 1;
            if (tt < 0 || tt >= T_) continue;
            float4 gv = make_float4(0.f, 0.f, 0.f, 0.f);
            if (alive) gv = *(const float4*)(gbase + (size_t)(tt * C_ + ci) * N_);
            ull in[4];
            in[0] = dup2(gv.x); in[1] = dup2(gv.y);
            in[2] = dup2(gv.z); in[3] = dup2(gv.w);
            const ulonglong2* wp = (const ulonglong2*)&w2s[(ci * 3 + kt) * 32 + co0];
            ulonglong2 wa = wp[0];
            ulonglong2 wb = wp[1];
            #pragma unroll
            for (int pt = 0; pt < 4; pt++) {
                ffma2(acc[pt][0], in[pt], wa.x);
                ffma2(acc[pt][1], in[pt], wa.y);
                ffma2(acc[pt][2], in[pt], wb.x);
                ffma2(acc[pt][3], in[pt], wb.y);
            }
        }
    }

    if (alive) {
        #pragma unroll
        for (int cp = 0; cp < 4; cp++) {
            float2 v0 = unpack2(acc[0][cp]);
            float2 v1 = unpack2(acc[1][cp]);
            float2 v2 = unpack2(acc[2][cp]);
            float2 v3 = unpack2(acc[3][cp]);
            int coA = co0 + 2 * cp;
            int coB = coA + 1;
            float4 lo = make_float4(v0.x, v1.x, v2.x, v3.x);
            float4 hi = make_float4(v0.y, v1.y, v2.y, v3.y);
            *(float4*)(out + ((size_t)(b * C_ + coA) * T_ + t) * N_ + nb) = lo;
            *(float4*)(out + ((size_t)(b * C_ + coB) * T_ + t) * N_ + nb) = hi;
        }
    }
}

// ---------------------------------------------------------------------------
// Launcher
// ---------------------------------------------------------------------------
extern "C" void kernel_launch(void* const* d_in, const int* in_sizes, int n_in,
                              void* d_out, int out_size) {
    const float* x     = (const float*)d_in[0];
    const void*  edges = d_in[1];
    const float* w1    = (const float*)d_in[2];
    const float* b1    = (const float*)d_in[3];
    const float* gcn_w = (const float*)d_in[4];
    const float* gcn_b = (const float*)d_in[5];
    const float* w2    = (const float*)d_in[6];
    const float* b2    = (const float*)d_in[7];
    float* out = (float*)d_out;

    dim3 g1(NBLK + 1, T_, B_);       // +1 block does CSR preprocessing
    k_conv1<<<g1, 256>>>(x, edges, w1, b1, gcn_w);

    dim3 ga(N_ / 8, BT_ / 4);
    k_agg<<<ga, 256>>>(gcn_b);

    dim3 g2(NBLK, T_, B_);
    k_conv2<<<g2, 256>>>(w2, b2, out);
}

// round 10
// speedup vs baseline: 1.7282x; 1.3060x over previous
#include <cuda_runtime.h>
#include <math.h>

// Problem constants (fixed shapes)
#define B_  4
#define C_  32
#define T_  48
#define N_  2000
#define E_  16000
#define BT_ (B_ * T_)   // 192

#define PTSB 256        // points per conv block
#define NBLK 8          // ceil(2000/256)
#define HSTRIDE 264     // htile row stride (words)
#define XWSTRIDE 34     // xw transpose tile row stride (words, EVEN for ST.64)

typedef unsigned long long ull;

// ---------------------------------------------------------------------------
// Scratch (device globals)
// ---------------------------------------------------------------------------
__device__ float g_xw[BT_ * N_ * C_];     // [g][n][c] (for gather)
__device__ float g_gout[BT_ * C_ * N_];   // [g][c][n] (for conv2 coalesced reads)
__device__ int   g_srcb[E_];
__device__ int   g_dstb[E_];
__device__ int   g_off[N_ + 1];
__device__ int   g_csr_src[E_];
__device__ float g_csr_w[E_];
__device__ float g_invdeg[N_];

// ---------------------------------------------------------------------------
// f32x2 helpers
// ---------------------------------------------------------------------------
__device__ __forceinline__ ull dup2(float x) {
    ull r;
    unsigned u = __float_as_uint(x);
    asm("mov.b64 %0, {%1, %1};" : "=l"(r) : "r"(u));
    return r;
}
__device__ __forceinline__ void ffma2(ull& acc, ull a, ull b) {
    asm("fma.rn.f32x2 %0, %1, %2, %0;" : "+l"(acc) : "l"(a), "l"(b));
}
__device__ __forceinline__ float2 unpack2(ull v) {
    unsigned lo, hi;
    asm("mov.b64 {%0, %1}, %2;" : "=r"(lo), "=r"(hi) : "l"(v));
    return make_float2(__uint_as_float(lo), __uint_as_float(hi));
}

// ---------------------------------------------------------------------------
// K1: fused conv1+relu+gcn_w GEMM (256 threads, 3 blocks/SM for reg headroom),
// with CSR preprocessing fused in as one extra block (blockIdx.x == NBLK).
// Thread map: cog = tid&3 (co0 = cog*8), ptg = tid>>2 (4 points each).
// ---------------------------------------------------------------------------
__global__ void __launch_bounds__(256, 3) k_conv1(
    const float* __restrict__ x,
    const void*  __restrict__ edges,
    const float* __restrict__ w1,
    const float* __restrict__ b1,
    const float* __restrict__ gcn_w)
{
    __shared__ __align__(16) union U {
        float pool[8704];                 // htile [32][264] / xwtile [256][34]
        struct {
            int   cnt[2000];
            int   off[2000];
            float dinv[2000];
            int   wsum[8];
            int   is64;
        } prep;
    } u;
    __shared__ __align__(16) float w1s[96 * 32];   // [(ci*3+kt)*32 + co]
    __shared__ __align__(16) float gws[32 * 32];   // [c2*32 + co]
    __shared__ __align__(16) float b1s[32];

    int tid = threadIdx.x;

    // ---------------- fused CSR preprocessing block ----------------
    if (blockIdx.x == NBLK) {
        if (blockIdx.y != 0 || blockIdx.z != 0) return;

        if (tid == 0) {
            const int* q = (const int*)edges;
            int ok = 1;
            #pragma unroll 1
            for (int i = 0; i < 64; i++) {
                if (q[2 * i + 1] != 0) { ok = 0; break; }
            }
            u.prep.is64 = ok;
        }
        for (int i = tid; i < N_; i += 256) u.prep.cnt[i] = 0;
        __syncthreads();
        const int is64 = u.prep.is64;

        #pragma unroll 1
        for (int e = tid; e < E_; e += 256) {
            int s, d;
            if (is64) {
                const long long* p = (const long long*)edges;
                s = (int)p[e];
                d = (int)p[E_ + e];
            } else {
                const int* p = (const int*)edges;
                s = p[e];
                d = p[E_ + e];
            }
            g_srcb[e] = s;
            g_dstb[e] = d;
            atomicAdd(&u.prep.cnt[d], 1);
        }
        __syncthreads();

        // block scan over 2000 counts (8 per thread, 256 threads)
        int lane = tid & 31, wid = tid >> 5;
        int base = tid * 8;
        int c[8];
        int sum = 0;
        #pragma unroll
        for (int i = 0; i < 8; i++) {
            int idx = base + i;
            c[i] = (idx < N_) ? u.prep.cnt[idx] : 0;
            sum += c[i];
        }
        int incl = sum;
        #pragma unroll
        for (int o = 1; o < 32; o <<= 1) {
            int v = __shfl_up_sync(0xffffffffu, incl, o);
            if (lane >= o) incl += v;
        }
        if (lane == 31) u.prep.wsum[wid] = incl;
        __syncthreads();
        int woff = 0;
        #pragma unroll
        for (int w = 0; w < 8; w++) woff += (w < wid) ? u.prep.wsum[w] : 0;
        int run = woff + incl - sum;
        #pragma unroll
        for (int i = 0; i < 8; i++) {
            int idx = base + i;
            if (idx < N_) {
                u.prep.off[idx] = run;
                g_off[idx] = run;
                float deg = (float)c[i] + 1.0f;
                u.prep.dinv[idx] = rsqrtf(deg);
                g_invdeg[idx] = 1.0f / deg;
            }
            run += c[i];
        }
        if (tid == 0) g_off[N_] = E_;
        __syncthreads();
        for (int i = tid; i < N_; i += 256) u.prep.cnt[i] = 0;
        __syncthreads();

        #pragma unroll 1
        for (int e = tid; e < E_; e += 256) {
            int s = g_srcb[e];
            int d = g_dstb[e];
            int pos = atomicAdd(&u.prep.cnt[d], 1);
            int idx = u.prep.off[d] + pos;
            g_csr_src[idx] = s;
            g_csr_w[idx] = u.prep.dinv[s] * u.prep.dinv[d];
        }
        return;
    }

    // ---------------- conv1 + gcn_w GEMM ----------------
    for (int i = tid; i < 96 * 32; i += 256) {
        int co = i & 31;
        int r = i >> 5;
        int kt = r % 3;
        int ci = r / 3;
        w1s[i] = w1[(co * C_ + ci) * 3 + kt];
    }
    for (int i = tid; i < 32 * 32; i += 256) gws[i] = gcn_w[i];
    if (tid < 32) b1s[tid] = b1[tid];
    __syncthreads();

    int cog = tid & 3;
    int ptg = tid >> 2;              // 0..63
    int co0 = cog * 8;
    int n0  = blockIdx.x * PTSB;
    int nb  = n0 + ptg * 4;
    bool alive = (nb < N_);
    int t = blockIdx.y;
    int b = blockIdx.z;

    // block-uniform validity of the three temporal taps
    bool v0 = (t - 1 >= 0);
    bool v2 = (t + 1 < T_);
    bool ld[3] = { v0 && alive, alive, v2 && alive };

    // Stage A: h = conv1(x) + b1
    ull acc[4][4];
    {
        const ull* bp = (const ull*)b1s;   // pairs (2c, 2c+1)
        #pragma unroll
        for (int cp = 0; cp < 4; cp++) {
            ull bq = bp[co0 / 2 + cp];
            #pragma unroll
            for (int pt = 0; pt < 4; pt++) acc[pt][cp] = bq;
        }
    }

    // pointer to the t-1 plane for ci=0
    const float* xrow = x + ((size_t)(b * C_ * T_) + (t - 1)) * N_ + nb;
    #pragma unroll 2
    for (int ci = 0; ci < 32; ci++) {
        const float* xr = xrow + ci * (T_ * N_);
        // 3 independent loads issued together (MLP>=3, x2 with unroll)
        float4 xv[3];
        #pragma unroll
        for (int kt = 0; kt < 3; kt++) {
            xv[kt] = ld[kt] ? *(const float4*)(xr + kt * N_)
                            : make_float4(0.f, 0.f, 0.f, 0.f);
        }
        #pragma unroll
        for (int kt = 0; kt < 3; kt++) {
            ull in[4];
            in[0] = dup2(xv[kt].x); in[1] = dup2(xv[kt].y);
            in[2] = dup2(xv[kt].z); in[3] = dup2(xv[kt].w);
            const ulonglong2* wp = (const ulonglong2*)&w1s[(ci * 3 + kt) * 32 + co0];
            ulonglong2 wa = wp[0];
            ulonglong2 wb = wp[1];
            #pragma unroll
            for (int pt = 0; pt < 4; pt++) {
                ffma2(acc[pt][0], in[pt], wa.x);
                ffma2(acc[pt][1], in[pt], wa.y);
                ffma2(acc[pt][2], in[pt], wb.x);
                ffma2(acc[pt][3], in[pt], wb.y);
            }
        }
    }

    // relu -> htile [co][pt]
    float* htile = u.pool;
    int pl = ptg * 4;
    #pragma unroll
    for (int pt = 0; pt < 4; pt++) {
        #pragma unroll
        for (int cp = 0; cp < 4; cp++) {
            float2 v = unpack2(acc[pt][cp]);
            htile[(co0 + 2 * cp) * HSTRIDE + pl + pt]     = fmaxf(v.x, 0.0f);
            htile[(co0 + 2 * cp + 1) * HSTRIDE + pl + pt] = fmaxf(v.y, 0.0f);
        }
    }
    __syncthreads();

    // Stage B: xw = h @ gcn_w
    ull xa[4][4];
    #pragma unroll
    for (int pt = 0; pt < 4; pt++)
        #pragma unroll
        for (int cp = 0; cp < 4; cp++) xa[pt][cp] = 0ull;

    #pragma unroll 4
    for (int c2 = 0; c2 < 32; c2++) {
        float4 hv = *(const float4*)&htile[c2 * HSTRIDE + pl];
        ull in[4];
        in[0] = dup2(hv.x); in[1] = dup2(hv.y);
        in[2] = dup2(hv.z); in[3] = dup2(hv.w);
        const ulonglong2* wp = (const ulonglong2*)&gws[c2 * 32 + co0];
        ulonglong2 wa = wp[0];
        ulonglong2 wb = wp[1];
        #pragma unroll
        for (int pt = 0; pt < 4; pt++) {
            ffma2(xa[pt][0], in[pt], wa.x);
            ffma2(xa[pt][1], in[pt], wa.y);
            ffma2(xa[pt][2], in[pt], wb.x);
            ffma2(xa[pt][3], in[pt], wb.y);
        }
    }
    __syncthreads();   // htile reads done before pool reuse

    // transpose to [pt][co] and store coalesced (XWSTRIDE even -> ST.64 ok)
    float* xwt = u.pool;
    #pragma unroll
    for (int pt = 0; pt < 4; pt++) {
        #pragma unroll
        for (int cp = 0; cp < 4; cp++) {
            float2 v = unpack2(xa[pt][cp]);
            *(float2*)&xwt[(pl + pt) * XWSTRIDE + co0 + 2 * cp] = v;
        }
    }
    __syncthreads();

    int g = b * T_ + t;
    float* dst = g_xw + ((size_t)g * N_ + n0) * C_;
    int rows = min(PTSB, N_ - n0);
    for (int i = tid; i < rows * C_; i += 256) {
        dst[i] = xwt[(i >> 5) * XWSTRIDE + (i & 31)];
    }
}

// ---------------------------------------------------------------------------
// K2: GCN aggregation; 4 graphs per warp (CSR loads amortized, MLP=8).
// Writes g_gout transposed [g][c][n].
// ---------------------------------------------------------------------------
__global__ void __launch_bounds__(256) k_agg(const float* __restrict__ gcn_b) {
    __shared__ __align__(16) float sbuf[4 * 256];   // [gg][lane*8+warp]
    int warp = threadIdx.x >> 5;
    int lane = threadIdx.x & 31;
    int n  = blockIdx.x * 8 + warp;
    int g0 = blockIdx.y * 4;

    int s0 = g_off[n];
    int s1 = g_off[n + 1];
    const float* __restrict__ xw0 = g_xw + (size_t)g0 * N_ * C_;
    const size_t GS = (size_t)N_ * C_;

    float acc[4] = {0.f, 0.f, 0.f, 0.f};
    int e = s0;
    for (; e + 1 < s1; e += 2) {
        int   sA = g_csr_src[e];
        int   sB = g_csr_src[e + 1];
        float wA = g_csr_w[e];
        float wB = g_csr_w[e + 1];
        float vA[4], vB[4];
        #pragma unroll
        for (int gg = 0; gg < 4; gg++) vA[gg] = __ldg(&xw0[gg * GS + sA * C_ + lane]);
        #pragma unroll
        for (int gg = 0; gg < 4; gg++) vB[gg] = __ldg(&xw0[gg * GS + sB * C_ + lane]);
        #pragma unroll
        for (int gg = 0; gg < 4; gg++) acc[gg] += wA * vA[gg] + wB * vB[gg];
    }
    if (e < s1) {
        int   sA = g_csr_src[e];
        float wA = g_csr_w[e];
        #pragma unroll
        for (int gg = 0; gg < 4; gg++) acc[gg] += wA * __ldg(&xw0[gg * GS + sA * C_ + lane]);
    }
    float idg = g_invdeg[n];
    float bia = gcn_b[lane];
    #pragma unroll
    for (int gg = 0; gg < 4; gg++) {
        acc[gg] += idg * xw0[gg * GS + n * C_ + lane] + bia;
        sbuf[gg * 256 + lane * 8 + warp] = acc[gg];
    }
    __syncthreads();

    // transposed store: [g][c][n0..n0+7]
    int n0 = blockIdx.x * 8;
    #pragma unroll
    for (int r = 0; r < 4; r++) {
        int idx = r * 256 + threadIdx.x;
        int gg = idx >> 8;
        int c  = (idx >> 3) & 31;
        int j  = idx & 7;
        g_gout[((size_t)(g0 + gg) * C_ + c) * N_ + n0 + j] = sbuf[gg * 256 + c * 8 + j];
    }
}

// ---------------------------------------------------------------------------
// K3: conv2 (256 threads, 3 blocks/SM); direct coalesced LDG from
// g_gout [g][c][n]; per-co float4 STG.128 output.
// ---------------------------------------------------------------------------
__global__ void __launch_bounds__(256, 3) k_conv2(
    const float* __restrict__ w2,
    const float* __restrict__ b2,
    float* __restrict__ out)
{
    __shared__ __align__(16) float w2s[96 * 32];   // [(ci*3+kt)*32 + co]
    __shared__ __align__(16) float b2s[32];

    int tid = threadIdx.x;
    for (int i = tid; i < 96 * 32; i += 256) {
        int co = i & 31;
        int r = i >> 5;
        int kt = r % 3;
        int ci = r / 3;
        w2s[i] = w2[(co * C_ + ci) * 3 + kt];
    }
    if (tid < 32) b2s[tid] = b2[tid];
    __syncthreads();

    int cog = tid & 3;
    int ptg = tid >> 2;
    int co0 = cog * 8;
    int n0  = blockIdx.x * PTSB;
    int nb  = n0 + ptg * 4;
    bool alive = (nb < N_);
    int t = blockIdx.y;
    int b = blockIdx.z;

    bool v0 = (t - 1 >= 0);
    bool v2 = (t + 1 < T_);
    bool ld[3] = { v0 && alive, alive, v2 && alive };

    ull acc[4][4];
    {
        const ull* bp = (const ull*)b2s;
        #pragma unroll
        for (int cp = 0; cp < 4; cp++) {
            ull bq = bp[co0 / 2 + cp];
            #pragma unroll
            for (int pt = 0; pt < 4; pt++) acc[pt][cp] = bq;
        }
    }

    // plane (t-1) for ci = 0
    const float* gbase = g_gout + ((size_t)(b * T_) + (t - 1)) * C_ * N_ + nb;
    #pragma unroll 2
    for (int ci = 0; ci < 32; ci++) {
        const float* gr = gbase + (size_t)ci * N_;
        float4 gv[3];
        #pragma unroll
        for (int kt = 0; kt < 3; kt++) {
            gv[kt] = ld[kt] ? *(const float4*)(gr + (size_t)kt * C_ * N_)
                            : make_float4(0.f, 0.f, 0.f, 0.f);
        }
        #pragma unroll
        for (int kt = 0; kt < 3; kt++) {
            ull in[4];
            in[0] = dup2(gv[kt].x); in[1] = dup2(gv[kt].y);
            in[2] = dup2(gv[kt].z); in[3] = dup2(gv[kt].w);
            const ulonglong2* wp = (const ulonglong2*)&w2s[(ci * 3 + kt) * 32 + co0];
            ulonglong2 wa = wp[0];
            ulonglong2 wb = wp[1];
            #pragma unroll
            for (int pt = 0; pt < 4; pt++) {
                ffma2(acc[pt][0], in[pt], wa.x);
                ffma2(acc[pt][1], in[pt], wa.y);
                ffma2(acc[pt][2], in[pt], wb.x);
                ffma2(acc[pt][3], in[pt], wb.y);
            }
        }
    }

    if (alive) {
        #pragma unroll
        for (int cp = 0; cp < 4; cp++) {
            float2 v0f = unpack2(acc[0][cp]);
            float2 v1f = unpack2(acc[1][cp]);
            float2 v2f = unpack2(acc[2][cp]);
            float2 v3f = unpack2(acc[3][cp]);
            int coA = co0 + 2 * cp;
            int coB = coA + 1;
            float4 lo = make_float4(v0f.x, v1f.x, v2f.x, v3f.x);
            float4 hi = make_float4(v0f.y, v1f.y, v2f.y, v3f.y);
            *(float4*)(out + ((size_t)(b * C_ + coA) * T_ + t) * N_ + nb) = lo;
            *(float4*)(out + ((size_t)(b * C_ + coB) * T_ + t) * N_ + nb) = hi;
        }
    }
}

// ---------------------------------------------------------------------------
// Launcher
// ---------------------------------------------------------------------------
extern "C" void kernel_launch(void* const* d_in, const int* in_sizes, int n_in,
                              void* d_out, int out_size) {
    const float* x     = (const float*)d_in[0];
    const void*  edges = d_in[1];
    const float* w1    = (const float*)d_in[2];
    const float* b1    = (const float*)d_in[3];
    const float* gcn_w = (const float*)d_in[4];
    const float* gcn_b = (const float*)d_in[5];
    const float* w2    = (const float*)d_in[6];
    const float* b2    = (const float*)d_in[7];
    float* out = (float*)d_out;

    dim3 g1(NBLK + 1, T_, B_);       // +1 block does CSR preprocessing
    k_conv1<<<g1, 256>>>(x, edges, w1, b1, gcn_w);

    dim3 ga(N_ / 8, BT_ / 4);
    k_agg<<<ga, 256>>>(gcn_b);

    dim3 g2(NBLK, T_, B_);
    k_conv2<<<g2, 256>>>(w2, b2, out);
}